// round 1
// baseline (speedup 1.0000x reference)
#include <cuda_runtime.h>

// Problem constants (match reference setup_inputs)
#define MAXN 50000
#define MAXE 400000
#define MAXTOT (MAXN + MAXE)   // edges + self loops
#define GAT_EPS 1e-5f

// ------------------------- scratch (device globals; no runtime alloc) ------
__device__ float g_xw [MAXN * 128];   // x @ W per layer ([N,128] or [N,40] for layer 3)
__device__ float g_aux[MAXN * 128];   // xres (layer1) / xw3 (layer3)
__device__ float g_h1 [MAXN * 128];
__device__ float g_h2 [MAXN * 128];
__device__ float g_agg[MAXN * 128];
__device__ float g_es [MAXN * 4];
__device__ float g_ed [MAXN * 4];
__device__ int   g_cnt[MAXN];
__device__ int   g_off[MAXN + 1];
__device__ int   g_cur[MAXN];
__device__ int   g_csr[MAXTOT];

// ------------------------- CSR build ---------------------------------------
__global__ void zcnt_kernel(int n) {
    int i = blockIdx.x * blockDim.x + threadIdx.x;
    if (i < n) g_cnt[i] = 0;
}

__global__ void histo_kernel(const int* __restrict__ dst, int E, int n) {
    int i = blockIdx.x * blockDim.x + threadIdx.x;
    if (i >= E + n) return;
    int dd = (i < E) ? dst[i] : (i - E);      // self loops appended
    atomicAdd(&g_cnt[dd], 1);
}

// single-block sequential-chunk exclusive scan over n counters
__global__ void scan_kernel(int n) {
    __shared__ int s[1024];
    __shared__ int carry_s;
    if (threadIdx.x == 0) carry_s = 0;
    __syncthreads();
    for (int base = 0; base < n; base += 1024) {
        int i = base + threadIdx.x;
        int v = (i < n) ? g_cnt[i] : 0;
        s[threadIdx.x] = v;
        __syncthreads();
        #pragma unroll
        for (int d = 1; d < 1024; d <<= 1) {
            int t = (threadIdx.x >= d) ? s[threadIdx.x - d] : 0;
            __syncthreads();
            s[threadIdx.x] += t;
            __syncthreads();
        }
        int c = carry_s;
        int exc = c + s[threadIdx.x] - v;
        if (i < n) { g_off[i] = exc; g_cur[i] = exc; }
        __syncthreads();
        if (threadIdx.x == 1023) carry_s = c + s[1023];
        __syncthreads();
    }
    if (threadIdx.x == 0) g_off[n] = carry_s;
}

__global__ void scatter_kernel(const int* __restrict__ src, const int* __restrict__ dst,
                               int E, int n) {
    int i = blockIdx.x * blockDim.x + threadIdx.x;
    if (i >= E + n) return;
    int ss, dd;
    if (i < E) { ss = src[i]; dd = dst[i]; }
    else       { ss = dd = i - E; }
    int p = atomicAdd(&g_cur[dd], 1);
    g_csr[p] = ss;
}

// ------------------------- SGEMM: C[M,128] = A[M,128] @ B[128,128] ---------
__global__ void sgemm128(const float* __restrict__ A, const float* __restrict__ B,
                         float* __restrict__ C, int M) {
    __shared__ float As[8][128];   // transposed A tile
    __shared__ float Bs[8][128];
    int row0 = blockIdx.x * 128;
    int tid  = threadIdx.x;
    int tx   = tid % 16, ty = tid / 16;
    float acc[8][8] = {};
    for (int k0 = 0; k0 < 128; k0 += 8) {
        {   // A tile: 128 rows x 8 cols, one float4 per thread
            int r = tid >> 1;
            int c = (tid & 1) * 4;
            int grow = row0 + r;
            float4 v = make_float4(0.f, 0.f, 0.f, 0.f);
            if (grow < M) v = *(const float4*)(A + (long)grow * 128 + k0 + c);
            As[c + 0][r] = v.x; As[c + 1][r] = v.y;
            As[c + 2][r] = v.z; As[c + 3][r] = v.w;
        }
        {   // B tile: 8 rows x 128 cols
            int r = tid >> 5;
            int c = (tid & 31) * 4;
            *(float4*)&Bs[r][c] = *(const float4*)(B + (k0 + r) * 128 + c);
        }
        __syncthreads();
        #pragma unroll
        for (int k = 0; k < 8; k++) {
            float4 a0 = *(float4*)&As[k][ty * 8];
            float4 a1 = *(float4*)&As[k][ty * 8 + 4];
            float4 b0 = *(float4*)&Bs[k][tx * 8];
            float4 b1 = *(float4*)&Bs[k][tx * 8 + 4];
            float af[8] = {a0.x, a0.y, a0.z, a0.w, a1.x, a1.y, a1.z, a1.w};
            float bf[8] = {b0.x, b0.y, b0.z, b0.w, b1.x, b1.y, b1.z, b1.w};
            #pragma unroll
            for (int i = 0; i < 8; i++)
                #pragma unroll
                for (int j = 0; j < 8; j++)
                    acc[i][j] += af[i] * bf[j];
        }
        __syncthreads();
    }
    #pragma unroll
    for (int i = 0; i < 8; i++) {
        int grow = row0 + ty * 8 + i;
        if (grow < M) {
            #pragma unroll
            for (int j = 0; j < 8; j += 4) {
                float4 v = make_float4(acc[i][j], acc[i][j+1], acc[i][j+2], acc[i][j+3]);
                *(float4*)(C + (long)grow * 128 + tx * 8 + j) = v;
            }
        }
    }
}

// ------------------------- small GEMM: C[M,40] = A[M,128] @ B[128,40] ------
__global__ void gemm40(const float* __restrict__ A, const float* __restrict__ B,
                       float* __restrict__ C, int M) {
    __shared__ float Ws[128 * 40];
    for (int i = threadIdx.x; i < 128 * 40; i += blockDim.x) Ws[i] = B[i];
    __syncthreads();
    int row  = blockIdx.x * 8 + (threadIdx.x >> 5);
    int lane = threadIdx.x & 31;
    if (row >= M) return;
    const float* a = A + (long)row * 128;
    float acc1 = 0.f, acc2 = 0.f;
    #pragma unroll 8
    for (int k = 0; k < 128; k++) {
        float av = __ldg(a + k);
        acc1 += av * Ws[k * 40 + lane];
        if (lane < 8) acc2 += av * Ws[k * 40 + 32 + lane];
    }
    C[(long)row * 40 + lane] = acc1;
    if (lane < 8) C[(long)row * 40 + 32 + lane] = acc2;
}

// ------------------------- attention logits (4 heads x 32ch) ---------------
__global__ void dots128(const float* __restrict__ xw,
                        const float* __restrict__ a_s, const float* __restrict__ a_d,
                        int n) {
    int node = blockIdx.x * 8 + (threadIdx.x >> 5);
    if (node >= n) return;
    int lane = threadIdx.x & 31;
    float4 xv  = *(const float4*)(xw + (long)node * 128 + lane * 4);
    float4 asv = *(const float4*)(a_s + lane * 4);
    float4 adv = *(const float4*)(a_d + lane * 4);
    float ps = xv.x * asv.x + xv.y * asv.y + xv.z * asv.z + xv.w * asv.w;
    float pd = xv.x * adv.x + xv.y * adv.y + xv.z * adv.z + xv.w * adv.w;
    // reduce within 8-lane head groups
    ps += __shfl_xor_sync(0xffffffffu, ps, 1);
    ps += __shfl_xor_sync(0xffffffffu, ps, 2);
    ps += __shfl_xor_sync(0xffffffffu, ps, 4);
    pd += __shfl_xor_sync(0xffffffffu, pd, 1);
    pd += __shfl_xor_sync(0xffffffffu, pd, 2);
    pd += __shfl_xor_sync(0xffffffffu, pd, 4);
    if ((lane & 7) == 0) {
        int h = lane >> 3;
        g_es[node * 4 + h] = ps;
        g_ed[node * 4 + h] = pd;
    }
}

__global__ void dots40(const float* __restrict__ xw,
                       const float* __restrict__ a_s, const float* __restrict__ a_d,
                       int n) {
    int node = blockIdx.x * 8 + (threadIdx.x >> 5);
    if (node >= n) return;
    int lane = threadIdx.x & 31;
    float x1 = xw[(long)node * 40 + lane];
    float x2 = (lane < 8) ? xw[(long)node * 40 + 32 + lane] : 0.f;
    float ps = x1 * a_s[lane] + ((lane < 8) ? x2 * a_s[32 + lane] : 0.f);
    float pd = x1 * a_d[lane] + ((lane < 8) ? x2 * a_d[32 + lane] : 0.f);
    #pragma unroll
    for (int o = 16; o; o >>= 1) {
        ps += __shfl_xor_sync(0xffffffffu, ps, o);
        pd += __shfl_xor_sync(0xffffffffu, pd, o);
    }
    if (lane == 0) { g_es[node] = ps; g_ed[node] = pd; }
}

// ------------------------- GAT aggregation (warp per node, online softmax) -
__global__ void agg128(const float* __restrict__ xw, float* __restrict__ out, int n) {
    int node = blockIdx.x * 8 + (threadIdx.x >> 5);
    if (node >= n) return;
    int lane = threadIdx.x & 31;
    int head = lane >> 3;                 // 4 consecutive channels per lane, one head
    float ed = g_ed[node * 4 + head];
    int s = g_off[node], e = g_off[node + 1];
    float m = -1e30f, d = 0.f;
    float4 acc = make_float4(0.f, 0.f, 0.f, 0.f);
    for (int i = s; i < e; i++) {
        int u = g_csr[i];
        float ev = g_es[u * 4 + head] + ed;
        ev = ev > 0.f ? ev : 0.2f * ev;   // LeakyReLU(0.2)
        float4 xv = *(const float4*)(xw + (long)u * 128 + lane * 4);
        if (ev <= m) {
            float w = __expf(ev - m);
            d += w;
            acc.x += w * xv.x; acc.y += w * xv.y;
            acc.z += w * xv.z; acc.w += w * xv.w;
        } else {
            float w = __expf(m - ev);
            d = d * w + 1.f;
            acc.x = acc.x * w + xv.x; acc.y = acc.y * w + xv.y;
            acc.z = acc.z * w + xv.z; acc.w = acc.w * w + xv.w;
            m = ev;
        }
    }
    float inv = 1.f / d;
    float4 o = make_float4(acc.x * inv, acc.y * inv, acc.z * inv, acc.w * inv);
    *(float4*)(out + (long)node * 128 + lane * 4) = o;
}

__global__ void agg40(const float* __restrict__ xw, const float* __restrict__ bias,
                      float* __restrict__ out, int n) {
    int node = blockIdx.x * 8 + (threadIdx.x >> 5);
    if (node >= n) return;
    int lane = threadIdx.x & 31;
    float ed = g_ed[node];
    int s = g_off[node], e = g_off[node + 1];
    float m = -1e30f, d = 0.f, a1 = 0.f, a2 = 0.f;
    for (int i = s; i < e; i++) {
        int u = g_csr[i];
        float ev = g_es[u] + ed;
        ev = ev > 0.f ? ev : 0.2f * ev;
        float x1 = xw[(long)u * 40 + lane];
        float x2 = (lane < 8) ? xw[(long)u * 40 + 32 + lane] : 0.f;
        if (ev <= m) {
            float w = __expf(ev - m);
            d += w; a1 += w * x1; a2 += w * x2;
        } else {
            float w = __expf(m - ev);
            d = d * w + 1.f; a1 = a1 * w + x1; a2 = a2 * w + x2;
            m = ev;
        }
    }
    float inv = 1.f / d;
    out[(long)node * 40 + lane] = a1 * inv + bias[lane];
    if (lane < 8) out[(long)node * 40 + 32 + lane] = a2 * inv + bias[32 + lane];
}

// ------------------------- bias + BN(eval) + residual + ELU ---------------
__global__ void postk(const float* __restrict__ agg, const float* __restrict__ bias,
                      const float* __restrict__ g, const float* __restrict__ be,
                      const float* __restrict__ mean, const float* __restrict__ var,
                      const float* __restrict__ res, float* __restrict__ out, int total) {
    int i = blockIdx.x * blockDim.x + threadIdx.x;
    if (i >= total) return;
    int c = i & 127;
    float xv = agg[i] + bias[c];
    xv = (xv - mean[c]) * rsqrtf(var[c] + GAT_EPS) * g[c] + be[c] + res[i];
    out[i] = xv > 0.f ? xv : expm1f(xv);
}

// ------------------------- launch ------------------------------------------
extern "C" void kernel_launch(void* const* d_in, const int* in_sizes, int n_in,
                              void* d_out, int out_size) {
    const float* x    = (const float*)d_in[0];
    const int*   ei   = (const int*)  d_in[1];
    const float* W1   = (const float*)d_in[2];
    const float* as1  = (const float*)d_in[3];
    const float* ad1  = (const float*)d_in[4];
    const float* b1   = (const float*)d_in[5];
    const float* W2   = (const float*)d_in[6];
    const float* as2  = (const float*)d_in[7];
    const float* ad2  = (const float*)d_in[8];
    const float* b2   = (const float*)d_in[9];
    const float* W3   = (const float*)d_in[10];
    const float* as3  = (const float*)d_in[11];
    const float* ad3  = (const float*)d_in[12];
    const float* b3   = (const float*)d_in[13];
    const float* Wres = (const float*)d_in[14];
    const float* g1   = (const float*)d_in[15];
    const float* be1  = (const float*)d_in[16];
    const float* m1   = (const float*)d_in[17];
    const float* v1   = (const float*)d_in[18];
    const float* g2   = (const float*)d_in[19];
    const float* be2  = (const float*)d_in[20];
    const float* m2   = (const float*)d_in[21];
    const float* v2   = (const float*)d_in[22];

    int n = in_sizes[0] / 128;
    int E = in_sizes[1] / 2;
    const int* src = ei;
    const int* dst = ei + E;
    int tot = E + n;

    float *p_xw, *p_aux, *p_h1, *p_h2, *p_agg;
    cudaGetSymbolAddress((void**)&p_xw,  g_xw);
    cudaGetSymbolAddress((void**)&p_aux, g_aux);
    cudaGetSymbolAddress((void**)&p_h1,  g_h1);
    cudaGetSymbolAddress((void**)&p_h2,  g_h2);
    cudaGetSymbolAddress((void**)&p_agg, g_agg);

    int nb_gemm = (n + 127) / 128;
    int nb_warp = (n + 7) / 8;
    int nb_elem = (n * 128 + 255) / 256;

    // CSR by dst (includes self loops)
    zcnt_kernel   <<<(n + 255) / 256, 256>>>(n);
    histo_kernel  <<<(tot + 255) / 256, 256>>>(dst, E, n);
    scan_kernel   <<<1, 1024>>>(n);
    scatter_kernel<<<(tot + 255) / 256, 256>>>(src, dst, E, n);

    // ---- layer 1 ----
    sgemm128<<<nb_gemm, 256>>>(x, W1,   p_xw,  n);
    sgemm128<<<nb_gemm, 256>>>(x, Wres, p_aux, n);
    dots128 <<<nb_warp, 256>>>(p_xw, as1, ad1, n);
    agg128  <<<nb_warp, 256>>>(p_xw, p_agg, n);
    postk   <<<nb_elem, 256>>>(p_agg, b1, g1, be1, m1, v1, p_aux, p_h1, n * 128);

    // ---- layer 2 ----
    sgemm128<<<nb_gemm, 256>>>(p_h1, W2, p_xw, n);
    dots128 <<<nb_warp, 256>>>(p_xw, as2, ad2, n);
    agg128  <<<nb_warp, 256>>>(p_xw, p_agg, n);
    postk   <<<nb_elem, 256>>>(p_agg, b2, g2, be2, m2, v2, p_h1, p_h2, n * 128);

    // ---- layer 3 (1 head, 40 channels, concat=False -> identity) ----
    gemm40<<<nb_warp, 256>>>(p_h2, W3, p_aux, n);
    dots40<<<nb_warp, 256>>>(p_aux, as3, ad3, n);
    agg40 <<<nb_warp, 256>>>(p_aux, b3, (float*)d_out, n);
}